// round 1
// baseline (speedup 1.0000x reference)
#include <cuda_runtime.h>
#include <math.h>

// Problem shapes (fixed by setup_inputs):
//   pos/vel/att: (8, 64, 32, 2) f32
//   W1 (64,128) b1(128) rms_w(128) W2(128,128) b2(128) Wa(128,256) ba(256)
//   out: (8,64,32,32,256) f32
// One CTA handles one (scene s, agent i): 32 pair rows (j) through the whole MLP.

#define NA      32
#define FEATK   64
#define LDA_F   65      // sF stride (bank-pad)
#define LDA_H   129     // sH1/sH2 stride
#define THREADS 128

// dynamic smem layout (floats)
#define OFF_F   0
#define OFF_H1  (OFF_F  + NA * LDA_F)          // 2080
#define OFF_H2  (OFF_H1 + NA * LDA_H)          // + 4128
#define OFF_W   (OFF_H2 + NA * LDA_H)          // + 4128
#define SMEM_FLOATS (OFF_W + 128 * 128)        // + 16384 = 26720
#define SMEM_BYTES  (SMEM_FLOATS * 4)          // 106880 B -> 2 CTAs/SM

__device__ __forceinline__ void sincos_red(float ang, float* s, float* c) {
    // manual range reduction so accuracy holds for |ang| up to ~128*pi
    // under both precise and fast-math sin/cos.
    float t = ang * 0.15915494309189535f;   // 1/(2*pi)
    t -= rintf(t);
    float a = t * 6.283185307179586f;
    *s = sinf(a);
    *c = cosf(a);
}

// C[32x128-chunk] += A[32xK] * W[Kx128], 4x8 microtile per thread.
__device__ __forceinline__ void gemm_acc(const float* __restrict__ sA, int lda,
                                         const float* __restrict__ sWm, int K,
                                         int r0, int c0, float acc[4][8]) {
#pragma unroll 4
    for (int k = 0; k < K; ++k) {
        float a[4];
#pragma unroll
        for (int r = 0; r < 4; ++r) a[r] = sA[(r0 + r) * lda + k];
        const float4 w0 = *(const float4*)(sWm + k * 128 + c0);
        const float4 w1 = *(const float4*)(sWm + k * 128 + c0 + 4);
        float w[8] = {w0.x, w0.y, w0.z, w0.w, w1.x, w1.y, w1.z, w1.w};
#pragma unroll
        for (int r = 0; r < 4; ++r)
#pragma unroll
            for (int c = 0; c < 8; ++c)
                acc[r][c] = fmaf(a[r], w[c], acc[r][c]);
    }
}

__global__ __launch_bounds__(THREADS, 2)
void relenc_kernel(const float* __restrict__ pos,
                   const float* __restrict__ vel,
                   const float* __restrict__ att,
                   const float* __restrict__ W1, const float* __restrict__ b1,
                   const float* __restrict__ rms_w,
                   const float* __restrict__ W2, const float* __restrict__ b2,
                   const float* __restrict__ Wa, const float* __restrict__ ba,
                   float* __restrict__ out) {
    extern __shared__ float smem[];
    float* sF  = smem + OFF_F;
    float* sH1 = smem + OFF_H1;
    float* sH2 = smem + OFF_H2;
    float* sW  = smem + OFF_W;

    const int tid = threadIdx.x;
    const int bx  = blockIdx.x;
    const int s   = bx >> 5;       // scene = b*T + t
    const int i   = bx & 31;       // agent i

    const int rg = tid >> 4;       // 0..7  -> rows r0 = rg*4
    const int cg = tid & 15;       // 0..15 -> cols c0 = cg*8
    const int r0 = rg * 4;
    const int c0 = cg * 8;
    const int lane = tid & 31;
    const int wid  = tid >> 5;

    // ---- stage W1 into smem (8192 floats) ----
    {
        float4* d = (float4*)sW;
        const float4* srcp = (const float4*)W1;
#pragma unroll
        for (int t = tid; t < (64 * 128) / 4; t += THREADS) d[t] = srcp[t];
    }

    // ---- features: 128 threads, j = tid&31, quarter q = tid>>5 ----
    {
        const float* P = pos + (size_t)s * NA * 2;
        const float* V = vel + (size_t)s * NA * 2;
        const float* A = att + (size_t)s * NA * 2;
        const int j = tid & 31;
        const int q = tid >> 5;

        float pix = P[2 * i], piy = P[2 * i + 1];
        float pjx = P[2 * j], pjy = P[2 * j + 1];
        float dx = pix - pjx, dy = piy - pjy;
        dx -= rintf(dx * (1.0f / 1024.0f)) * 1024.0f;   // rintf == round-half-even
        dy -= rintf(dy * (1.0f / 1024.0f)) * 1024.0f;

        float* fr = sF + j * LDA_F;
        if (q == 0) {
            float vix = V[2 * i], viy = V[2 * i + 1];
            float vjx = V[2 * j], vjy = V[2 * j + 1];
            float dvx = vix - vjx, dvy = viy - vjy;
            float dist = sqrtf(dx * dx + dy * dy) + 1e-6f;
            float dirx = dx / dist, diry = dy / dist;
            float rel  = sqrtf(dvx * dvx + dvy * dvy);
            float clos = (dvx * dx + dvy * dy) / dist;
            float invd = 1.0f / (dist + 0.1f);
            float logd = logf(dist + 1.0f);
            float tti  = dist / fmaxf(clos, 0.001f);
            float aix = A[2 * i], aiy = A[2 * i + 1];
            float ajx = A[2 * j], ajy = A[2 * j + 1];
            fr[0] = dx;   fr[1] = dy;
            fr[2] = dvx;  fr[3] = dvy;
            fr[4] = dist; fr[5] = invd;
            fr[6] = rel;  fr[7] = clos;
            fr[8] = dirx; fr[9] = diry;
            fr[10] = logd; fr[11] = tti;
            fr[12] = dirx * aix + diry * aiy;
            fr[13] = dirx * aiy - diry * aix;
            fr[14] = -(dirx * ajx + diry * ajy);
            fr[15] = -dirx * ajy + diry * ajx;
            fr[16] = aix * ajx + aiy * ajy;
            fr[17] = aix * ajy - aiy * ajx;
        } else {
            const float C = (float)(6.283185307179586476925287 / 1024.0);
            float spx = dx * C, spy = dy * C;
            int b0 = (q == 1) ? 0 : (q == 2) ? 3 : 6;
            int nb = (q == 3) ? 2 : 3;
            for (int b = b0; b < b0 + nb; ++b) {
                float f = (float)(1 << b);
                float sx, cx, sy, cy;
                sincos_red(spx * f, &sx, &cx);
                sincos_red(spy * f, &sy, &cy);
                fr[18 + 4 * b + 0] = sx;
                fr[18 + 4 * b + 1] = sy;
                fr[18 + 4 * b + 2] = cx;
                fr[18 + 4 * b + 3] = cy;
            }
            if (q == 3) {
#pragma unroll
                for (int c = 50; c < 64; ++c) fr[c] = 0.0f;
            }
        }
    }
    __syncthreads();

    // ---- GEMM1: h1 = feat @ W1 + b1 ----
    {
        float acc[4][8];
#pragma unroll
        for (int r = 0; r < 4; ++r)
#pragma unroll
            for (int c = 0; c < 8; ++c) acc[r][c] = 0.0f;
        gemm_acc(sF, LDA_F, sW, FEATK, r0, c0, acc);
        float4 bb0 = *(const float4*)(b1 + c0);
        float4 bb1 = *(const float4*)(b1 + c0 + 4);
        float bb[8] = {bb0.x, bb0.y, bb0.z, bb0.w, bb1.x, bb1.y, bb1.z, bb1.w};
#pragma unroll
        for (int r = 0; r < 4; ++r)
#pragma unroll
            for (int c = 0; c < 8; ++c)
                sH1[(r0 + r) * LDA_H + c0 + c] = acc[r][c] + bb[c];
    }
    __syncthreads();

    // ---- rmsnorm + silu over each row of sH1 (4 warps, 8 rows each) ----
    for (int r = wid; r < NA; r += 4) {
        float* hr = sH1 + r * LDA_H;
        float v[4];
        float ss = 0.0f;
#pragma unroll
        for (int q = 0; q < 4; ++q) {
            v[q] = hr[lane + 32 * q];
            ss += v[q] * v[q];
        }
#pragma unroll
        for (int o = 16; o > 0; o >>= 1) ss += __shfl_xor_sync(0xffffffffu, ss, o);
        float scale = rsqrtf(ss * (1.0f / 128.0f) + 1e-5f);
#pragma unroll
        for (int q = 0; q < 4; ++q) {
            float x = v[q] * scale * rms_w[lane + 32 * q];
            hr[lane + 32 * q] = x / (1.0f + expf(-x));
        }
    }
    __syncthreads();

    // ---- stage W2 (16384 floats) ----
    {
        float4* d = (float4*)sW;
        const float4* srcp = (const float4*)W2;
#pragma unroll
        for (int t = tid; t < (128 * 128) / 4; t += THREADS) d[t] = srcp[t];
    }
    __syncthreads();

    // ---- GEMM2: h2 = h1 @ W2 + b2 ----
    {
        float acc[4][8];
#pragma unroll
        for (int r = 0; r < 4; ++r)
#pragma unroll
            for (int c = 0; c < 8; ++c) acc[r][c] = 0.0f;
        gemm_acc(sH1, LDA_H, sW, 128, r0, c0, acc);
        float4 bb0 = *(const float4*)(b2 + c0);
        float4 bb1 = *(const float4*)(b2 + c0 + 4);
        float bb[8] = {bb0.x, bb0.y, bb0.z, bb0.w, bb1.x, bb1.y, bb1.z, bb1.w};
#pragma unroll
        for (int r = 0; r < 4; ++r)
#pragma unroll
            for (int c = 0; c < 8; ++c)
                sH2[(r0 + r) * LDA_H + c0 + c] = acc[r][c] + bb[c];
    }
    __syncthreads();

    // ---- GEMM3: out = h2 @ Wa + ba, two 128-col halves ----
    for (int half = 0; half < 2; ++half) {
        // stage Wa[:, half*128 : half*128+128]  (16384 floats)
        {
            float4* d = (float4*)sW;
            const float4* srcp = (const float4*)Wa;
#pragma unroll
            for (int t = tid; t < 4096; t += THREADS) {
                int k  = t >> 5;          // 32 float4 per 128-col row
                int c4 = t & 31;
                d[t] = srcp[(size_t)k * 64 + half * 32 + c4];
            }
        }
        __syncthreads();

        float acc[4][8];
#pragma unroll
        for (int r = 0; r < 4; ++r)
#pragma unroll
            for (int c = 0; c < 8; ++c) acc[r][c] = 0.0f;
        gemm_acc(sH2, LDA_H, sW, 128, r0, c0, acc);

        float4 bb0 = *(const float4*)(ba + half * 128 + c0);
        float4 bb1 = *(const float4*)(ba + half * 128 + c0 + 4);
        size_t obase = (size_t)bx * (NA * 256) + (size_t)half * 128 + c0;
#pragma unroll
        for (int r = 0; r < 4; ++r) {
            float4 o0, o1;
            o0.x = acc[r][0] + bb0.x; o0.y = acc[r][1] + bb0.y;
            o0.z = acc[r][2] + bb0.z; o0.w = acc[r][3] + bb0.w;
            o1.x = acc[r][4] + bb1.x; o1.y = acc[r][5] + bb1.y;
            o1.z = acc[r][6] + bb1.z; o1.w = acc[r][7] + bb1.w;
            float* op = out + obase + (size_t)(r0 + r) * 256;
            *(float4*)(op)     = o0;
            *(float4*)(op + 4) = o1;
        }
        __syncthreads();   // sW will be overwritten by next half
    }
}

extern "C" void kernel_launch(void* const* d_in, const int* in_sizes, int n_in,
                              void* d_out, int out_size) {
    const float* pos   = (const float*)d_in[0];
    const float* vel   = (const float*)d_in[1];
    const float* att   = (const float*)d_in[2];
    const float* W1    = (const float*)d_in[3];
    const float* b1    = (const float*)d_in[4];
    const float* rms_w = (const float*)d_in[5];
    const float* W2    = (const float*)d_in[6];
    const float* b2    = (const float*)d_in[7];
    const float* Wa    = (const float*)d_in[8];
    const float* ba    = (const float*)d_in[9];
    // d_in[10] = layer_idx (unused)

    int grid = in_sizes[0] / 2;   // B*T*N = 16384 CTAs, one per (scene, i)

    cudaFuncSetAttribute(relenc_kernel,
                         cudaFuncAttributeMaxDynamicSharedMemorySize, SMEM_BYTES);
    relenc_kernel<<<grid, THREADS, SMEM_BYTES>>>(
        pos, vel, att, W1, b1, rms_w, W2, b2, Wa, ba, (float*)d_out);
}

// round 3
// speedup vs baseline: 3.5066x; 3.5066x over previous
#include <cuda_runtime.h>
#include <cstdint>
#include <math.h>

// RelationalEncoder, sm_103 target: tensor cores via mma.sync.m16n8k8 tf32.
// CTA = 256 threads = 256 pair rows (8 agents x 32 partners), grid = 2048.
// GEMMs: [256x64]@[64x128] -> rms+silu -> @[128x128] -> @[128x256].

#define THREADS 256

// smem layout (bytes)
#define H_STRIDE 132              // floats per row (128 + 4 pad -> 4-bank shift)
#define F_STRIDE 68               // feature buffer stride (64 + 4 pad)
#define OFF_H    0                                    // 256*132*4 = 135168 (F overlays this)
#define OFF_W    135168                               // 128*132*4 = 67584 max
#define OFF_BIAS (OFF_W + 67584)                      // 640 floats = 2560
#define SMEM_BYTES (OFF_BIAS + 2560)                  // 205312

static __device__ __forceinline__ uint32_t f2tf32(float v) {
    uint32_t r;
    asm("cvt.rna.tf32.f32 %0, %1;" : "=r"(r) : "f"(v));
    return r;
}

static __device__ __forceinline__ void mma_tf32(float* c, uint32_t a0, uint32_t a1,
                                                uint32_t a2, uint32_t a3,
                                                uint32_t b0, uint32_t b1) {
    asm volatile(
        "mma.sync.aligned.m16n8k8.row.col.f32.tf32.tf32.f32 "
        "{%0,%1,%2,%3}, {%4,%5,%6,%7}, {%8,%9}, {%0,%1,%2,%3};"
        : "+f"(c[0]), "+f"(c[1]), "+f"(c[2]), "+f"(c[3])
        : "r"(a0), "r"(a1), "r"(a2), "r"(a3), "r"(b0), "r"(b1));
}

// One fused GEMM pass: C[256 x 128] += A[256 x K] * W^T  (W staged as Wt[n][k]).
// Warp (mw, nw): rows mrow0..+64, cols {half*64 + nw*32 + nt*8}, acc[2][4][4][4].
static __device__ __forceinline__ void gemm_tile(const uint32_t* __restrict__ A, int as,
                                                 const uint32_t* __restrict__ W, int ws,
                                                 int ksteps, int mrow0, int nwoff,
                                                 int lq, int lr, float* __restrict__ acc) {
    for (int ks = 0; ks < ksteps; ++ks) {
        const int k0 = ks * 8;
        uint32_t a[16];
#pragma unroll
        for (int mt = 0; mt < 4; ++mt) {
            const uint32_t* Ap = A + (mrow0 + mt * 16 + lq) * as + k0 + lr;
            a[mt * 4 + 0] = Ap[0];
            a[mt * 4 + 1] = Ap[8 * as];
            a[mt * 4 + 2] = Ap[4];
            a[mt * 4 + 3] = Ap[8 * as + 4];
        }
#pragma unroll
        for (int half = 0; half < 2; ++half) {
#pragma unroll
            for (int nt = 0; nt < 4; ++nt) {
                const int n = half * 64 + nwoff + nt * 8 + lq;
                const uint32_t b0 = W[n * ws + k0 + lr];
                const uint32_t b1 = W[n * ws + k0 + lr + 4];
#pragma unroll
                for (int mt = 0; mt < 4; ++mt) {
                    float* c = acc + (((half * 4 + nt) * 4 + mt) << 2);
                    mma_tf32(c, a[mt * 4], a[mt * 4 + 1], a[mt * 4 + 2], a[mt * 4 + 3],
                             b0, b1);
                }
            }
        }
    }
}

__global__ __launch_bounds__(THREADS, 1)
void relenc_mma(const float* __restrict__ pos,
                const float* __restrict__ vel,
                const float* __restrict__ att,
                const float* __restrict__ W1, const float* __restrict__ b1,
                const float* __restrict__ rms_w,
                const float* __restrict__ W2, const float* __restrict__ b2,
                const float* __restrict__ Wa, const float* __restrict__ ba,
                float* __restrict__ out) {
    extern __shared__ char smem[];
    float*    Hf = (float*)(smem + OFF_H);      // fp32 view
    uint32_t* Hu = (uint32_t*)(smem + OFF_H);   // tf32 view (same slots)
    uint32_t* Wt = (uint32_t*)(smem + OFF_W);
    float*    sB = (float*)(smem + OFF_BIAS);   // b1|b2|ba0|ba1|rms_w

    const int tid  = threadIdx.x;
    const int wid  = tid >> 5;
    const int lane = tid & 31;
    const int lq   = lane >> 2;
    const int lr   = lane & 3;
    const int nw    = wid & 1;
    const int mw    = wid >> 1;
    const int mrow0 = mw * 64;
    const int nwoff = nw * 32;
    const int bx = blockIdx.x;
    const int s  = bx >> 2;         // scene
    const int qd = bx & 3;          // agent quarter
    const int i  = qd * 8 + wid;    // agent i (warp-wide)
    const int j  = lane;            // partner j

    // ---- stage biases ----
    if (tid < 128) {
        sB[tid]       = b1[tid];
        sB[128 + tid] = b2[tid];
        sB[256 + tid] = ba[tid];
        sB[384 + tid] = ba[128 + tid];
        sB[512 + tid] = rms_w[tid];
    }

    // ---- stage W1^T as Wt[n][k], tf32, stride 68 ----
#pragma unroll
    for (int it = 0; it < 32; ++it) {
        int idx = tid + it * THREADS;          // 8192 elems, idx = k*128+n
        int n = idx & 127, k = idx >> 7;
        Wt[n * F_STRIDE + k] = f2tf32(W1[idx]);
    }

    // ---- features: thread = one pair row, write tf32 to F (overlays H) ----
    {
        const float* P = pos + (size_t)s * 64;
        const float* V = vel + (size_t)s * 64;
        const float* A = att + (size_t)s * 64;
        float f[64];
        float dx = P[2 * i] - P[2 * j], dy = P[2 * i + 1] - P[2 * j + 1];
        dx -= rintf(dx * (1.0f / 1024.0f)) * 1024.0f;
        dy -= rintf(dy * (1.0f / 1024.0f)) * 1024.0f;
        float dvx = V[2 * i] - V[2 * j], dvy = V[2 * i + 1] - V[2 * j + 1];
        float dist = sqrtf(dx * dx + dy * dy) + 1e-6f;
        float inv = 1.0f / dist;
        float dirx = dx * inv, diry = dy * inv;
        float clos = (dvx * dx + dvy * dy) * inv;
        float aix = A[2 * i], aiy = A[2 * i + 1];
        float ajx = A[2 * j], ajy = A[2 * j + 1];
        f[0] = dx;  f[1] = dy;  f[2] = dvx; f[3] = dvy;
        f[4] = dist;
        f[5] = 1.0f / (dist + 0.1f);
        f[6] = sqrtf(dvx * dvx + dvy * dvy);
        f[7] = clos;
        f[8] = dirx; f[9] = diry;
        f[10] = logf(dist + 1.0f);
        f[11] = dist / fmaxf(clos, 0.001f);
        f[12] = dirx * aix + diry * aiy;
        f[13] = dirx * aiy - diry * aix;
        f[14] = -(dirx * ajx + diry * ajy);
        f[15] = -dirx * ajy + diry * ajx;
        f[16] = aix * ajx + aiy * ajy;
        f[17] = aix * ajy - aiy * ajx;
        const float C = (float)(6.283185307179586476925287 / 1024.0);
        const float TWO_PI = 6.283185307179586f;
        float spx = dx * C, spy = dy * C;
#pragma unroll
        for (int b = 0; b < 8; ++b) {
            float fb = (float)(1 << b);
            float tx = spx * fb * 0.15915494309189535f; tx -= rintf(tx);
            float ty = spy * fb * 0.15915494309189535f; ty -= rintf(ty);
            float ax = tx * TWO_PI, ay = ty * TWO_PI;
            f[18 + 4 * b + 0] = __sinf(ax);
            f[18 + 4 * b + 1] = __sinf(ay);
            f[18 + 4 * b + 2] = __cosf(ax);
            f[18 + 4 * b + 3] = __cosf(ay);
        }
#pragma unroll
        for (int c = 50; c < 64; ++c) f[c] = 0.0f;
        uint32_t* fr = Hu + tid * F_STRIDE;
#pragma unroll
        for (int c = 0; c < 64; ++c) fr[c] = f2tf32(f[c]);
    }
    __syncthreads();

    float acc[128];

    // ================= GEMM1: D = feat @ W1 =================
#pragma unroll
    for (int q = 0; q < 128; ++q) acc[q] = 0.0f;
    gemm_tile(Hu, F_STRIDE, Wt, F_STRIDE, 8, mrow0, nwoff, lq, lr, acc);
    __syncthreads();   // all warps done reading F before H overwrites it

    // epilogue 1: H = D + b1 (fp32)
#pragma unroll
    for (int half = 0; half < 2; ++half)
#pragma unroll
        for (int nt = 0; nt < 4; ++nt) {
            const int c0 = half * 64 + nwoff + nt * 8 + 2 * lr;
#pragma unroll
            for (int mt = 0; mt < 4; ++mt) {
                const int r0 = mrow0 + mt * 16 + lq;
                const float* c = acc + (((half * 4 + nt) * 4 + mt) << 2);
                Hf[r0 * H_STRIDE + c0]           = c[0] + sB[c0];
                Hf[r0 * H_STRIDE + c0 + 1]       = c[1] + sB[c0 + 1];
                Hf[(r0 + 8) * H_STRIDE + c0]     = c[2] + sB[c0];
                Hf[(r0 + 8) * H_STRIDE + c0 + 1] = c[3] + sB[c0 + 1];
            }
        }
    __syncthreads();

    // rmsnorm + silu (thread = one row), then stage W2^T
    {
        const float* hr = Hf + tid * H_STRIDE;
        float ss = 0.0f;
#pragma unroll
        for (int c = 0; c < 128; ++c) { float x = hr[c]; ss = fmaf(x, x, ss); }
        float sc = rsqrtf(ss * (1.0f / 128.0f) + 1e-5f);
        uint32_t* hw = Hu + tid * H_STRIDE;
#pragma unroll
        for (int c = 0; c < 128; ++c) {
            float x = hr[c] * sc * sB[512 + c];
            hw[c] = f2tf32(x / (1.0f + __expf(-x)));
        }
    }
#pragma unroll
    for (int it = 0; it < 64; ++it) {
        int idx = tid + it * THREADS;          // 16384, idx = k*128+n
        int n = idx & 127, k = idx >> 7;
        Wt[n * H_STRIDE + k] = f2tf32(W2[idx]);
    }
    __syncthreads();

    // ================= GEMM2: D = h1 @ W2 =================
#pragma unroll
    for (int q = 0; q < 128; ++q) acc[q] = 0.0f;
    gemm_tile(Hu, H_STRIDE, Wt, H_STRIDE, 16, mrow0, nwoff, lq, lr, acc);
    __syncthreads();

    // epilogue 2: H = tf32(D + b2); stage Wa half 0
#pragma unroll
    for (int half = 0; half < 2; ++half)
#pragma unroll
        for (int nt = 0; nt < 4; ++nt) {
            const int c0 = half * 64 + nwoff + nt * 8 + 2 * lr;
#pragma unroll
            for (int mt = 0; mt < 4; ++mt) {
                const int r0 = mrow0 + mt * 16 + lq;
                const float* c = acc + (((half * 4 + nt) * 4 + mt) << 2);
                Hu[r0 * H_STRIDE + c0]           = f2tf32(c[0] + sB[128 + c0]);
                Hu[r0 * H_STRIDE + c0 + 1]       = f2tf32(c[1] + sB[128 + c0 + 1]);
                Hu[(r0 + 8) * H_STRIDE + c0]     = f2tf32(c[2] + sB[128 + c0]);
                Hu[(r0 + 8) * H_STRIDE + c0 + 1] = f2tf32(c[3] + sB[128 + c0 + 1]);
            }
        }
#pragma unroll
    for (int it = 0; it < 64; ++it) {
        int idx = tid + it * THREADS;          // 16384, idx = k*128+n (n in [0,128))
        int n = idx & 127, k = idx >> 7;
        Wt[n * H_STRIDE + k] = f2tf32(Wa[(size_t)k * 256 + n]);
    }
    __syncthreads();

    // ================= GEMM3 half A: out[:,0:128] =================
#pragma unroll
    for (int q = 0; q < 128; ++q) acc[q] = 0.0f;
    gemm_tile(Hu, H_STRIDE, Wt, H_STRIDE, 16, mrow0, nwoff, lq, lr, acc);
    __syncthreads();   // Wa half 1 will overwrite Wt

    // epilogue 3a -> global; stage Wa half 1
    {
        float* ob = out + (size_t)bx * 256 * 256;
#pragma unroll
        for (int half = 0; half < 2; ++half)
#pragma unroll
            for (int nt = 0; nt < 4; ++nt) {
                const int c0 = half * 64 + nwoff + nt * 8 + 2 * lr;
#pragma unroll
                for (int mt = 0; mt < 4; ++mt) {
                    const int r0 = mrow0 + mt * 16 + lq;
                    const float* c = acc + (((half * 4 + nt) * 4 + mt) << 2);
                    float2 v0 = {c[0] + sB[256 + c0], c[1] + sB[256 + c0 + 1]};
                    float2 v1 = {c[2] + sB[256 + c0], c[3] + sB[256 + c0 + 1]};
                    *(float2*)(ob + (size_t)r0 * 256 + c0)       = v0;
                    *(float2*)(ob + (size_t)(r0 + 8) * 256 + c0) = v1;
                }
            }
    }
#pragma unroll
    for (int it = 0; it < 64; ++it) {
        int idx = tid + it * THREADS;
        int n = idx & 127, k = idx >> 7;
        Wt[n * H_STRIDE + k] = f2tf32(Wa[(size_t)k * 256 + 128 + n]);
    }
    __syncthreads();

    // ================= GEMM3 half B: out[:,128:256] =================
#pragma unroll
    for (int q = 0; q < 128; ++q) acc[q] = 0.0f;
    gemm_tile(Hu, H_STRIDE, Wt, H_STRIDE, 16, mrow0, nwoff, lq, lr, acc);

    {
        float* ob = out + (size_t)bx * 256 * 256 + 128;
#pragma unroll
        for (int half = 0; half < 2; ++half)
#pragma unroll
            for (int nt = 0; nt < 4; ++nt) {
                const int c0 = half * 64 + nwoff + nt * 8 + 2 * lr;
#pragma unroll
                for (int mt = 0; mt < 4; ++mt) {
                    const int r0 = mrow0 + mt * 16 + lq;
                    const float* c = acc + (((half * 4 + nt) * 4 + mt) << 2);
                    float2 v0 = {c[0] + sB[384 + c0], c[1] + sB[384 + c0 + 1]};
                    float2 v1 = {c[2] + sB[384 + c0], c[3] + sB[384 + c0 + 1]};
                    *(float2*)(ob + (size_t)r0 * 256 + c0)       = v0;
                    *(float2*)(ob + (size_t)(r0 + 8) * 256 + c0) = v1;
                }
            }
    }
}

extern "C" void kernel_launch(void* const* d_in, const int* in_sizes, int n_in,
                              void* d_out, int out_size) {
    const float* pos   = (const float*)d_in[0];
    const float* vel   = (const float*)d_in[1];
    const float* att   = (const float*)d_in[2];
    const float* W1    = (const float*)d_in[3];
    const float* b1    = (const float*)d_in[4];
    const float* rms_w = (const float*)d_in[5];
    const float* W2    = (const float*)d_in[6];
    const float* b2    = (const float*)d_in[7];
    const float* Wa    = (const float*)d_in[8];
    const float* ba    = (const float*)d_in[9];

    static int inited = 0;
    if (!inited) {
        cudaFuncSetAttribute(relenc_mma,
                             cudaFuncAttributeMaxDynamicSharedMemorySize, SMEM_BYTES);
        inited = 1;
    }
    int grid = in_sizes[0] / 16;   // B*T*N*2 / 16 = 2048 CTAs of 256 rows
    relenc_mma<<<grid, THREADS, SMEM_BYTES>>>(
        pos, vel, att, W1, b1, rms_w, W2, b2, Wa, ba, (float*)d_out);
}